// round 2
// baseline (speedup 1.0000x reference)
#include <cuda_runtime.h>
#include <math.h>

// Problem constants (fixed by setup_inputs)
#define BB 64
#define LL 512
#define NNCH 64
#define AAA 64
#define DDD 256
#define PPP 16

// Scratch (no cudaMalloc allowed)
__device__ float g_partial[BB * 2 * 32];

// -------- packed fp32x2 FMA (Blackwell FFMA2) --------
__device__ __forceinline__ void fma2(unsigned long long& c, unsigned long long a,
                                     unsigned long long b) {
    asm("fma.rn.f32x2 %0, %1, %2, %0;" : "+l"(c) : "l"(a), "l"(b));
}
__device__ __forceinline__ ulonglong2 as_ull2(float4 v) {
    return *reinterpret_cast<ulonglong2*>(&v);
}
__device__ __forceinline__ float2 as_f2(unsigned long long v) {
    return *reinterpret_cast<float2*>(&v);
}

// ============================================================================
// Kernel 1: Conv1d(N->32, k=3, pad=1) -> ReLU -> partial sum over half of L.
// grid (2, B): blockIdx.x = half h, blockIdx.y = b. 256 threads (8 warps).
// Warp w owns output channels o0..o0+3 (o0 = 4w); lane = l within 32-wide tile.
// ============================================================================
__global__ __launch_bounds__(256) void conv_pool_kernel(
    const float* __restrict__ x, const float* __restrict__ conv_w,
    const float* __restrict__ conv_b) {
    // sx: 34 rows x 64 floats, pitch 17 float4 (68 floats) => conflict-free for
    // lane-varying-row LDS.128 (68 mod 32 = 4 -> 8-lane phase hits 32 distinct banks)
    __shared__ float4 sx4[34 * 17];
    __shared__ float4 sw4[32 * 3 * 16];  // [o][k][i] layout, broadcast reads

    const int t = threadIdx.x;
    const int h = blockIdx.x, b = blockIdx.y;

    // Load conv_w (32,64,3) -> sw[o][k][i]
    for (int u = t; u < 32 * 64 * 3; u += 256) {
        int o = u / 192;
        int rem = u % 192;
        int i = rem / 3;
        int k = rem % 3;
        reinterpret_cast<float*>(sw4)[(o * 3 + k) * 64 + i] = conv_w[u];
    }

    const int w = t >> 5, lane = t & 31;
    const int o0 = w * 4;
    // hoist bias to registers (read once, not per tile)
    const float cb0 = conv_b[o0 + 0], cb1 = conv_b[o0 + 1];
    const float cb2 = conv_b[o0 + 2], cb3 = conv_b[o0 + 3];
    float pool0 = 0.f, pool1 = 0.f, pool2 = 0.f, pool3 = 0.f;
    const float4* x4 = reinterpret_cast<const float4*>(x);

    for (int tile = 0; tile < 8; tile++) {
        const int row0 = h * 256 + tile * 32 - 1;  // first global row of slab
        __syncthreads();  // protects sw (iter 0) and previous tile's sx reads
        for (int u = t; u < 34 * 16; u += 256) {
            int r = u >> 4, i4 = u & 15;
            int gr = row0 + r;
            float4 v = make_float4(0.f, 0.f, 0.f, 0.f);
            if (gr >= 0 && gr < LL) v = x4[(b * LL + gr) * 16 + i4];
            sx4[r * 17 + i4] = v;
        }
        __syncthreads();

        unsigned long long acc0 = 0ull, acc1 = 0ull, acc2 = 0ull, acc3 = 0ull;
#pragma unroll
        for (int k = 0; k < 3; k++) {
#pragma unroll
            for (int i4 = 0; i4 < 16; i4++) {
                float4 xv = sx4[(lane + k) * 17 + i4];
                ulonglong2 xp = as_ull2(xv);
                float4 wv0 = sw4[((o0 + 0) * 3 + k) * 16 + i4];
                float4 wv1 = sw4[((o0 + 1) * 3 + k) * 16 + i4];
                float4 wv2 = sw4[((o0 + 2) * 3 + k) * 16 + i4];
                float4 wv3 = sw4[((o0 + 3) * 3 + k) * 16 + i4];
                ulonglong2 w0 = as_ull2(wv0), w1 = as_ull2(wv1);
                ulonglong2 w2 = as_ull2(wv2), w3 = as_ull2(wv3);
                fma2(acc0, xp.x, w0.x);
                fma2(acc0, xp.y, w0.y);
                fma2(acc1, xp.x, w1.x);
                fma2(acc1, xp.y, w1.y);
                fma2(acc2, xp.x, w2.x);
                fma2(acc2, xp.y, w2.y);
                fma2(acc3, xp.x, w3.x);
                fma2(acc3, xp.y, w3.y);
            }
        }
        // epilogue for this tile: bias -> relu -> accumulate (per-lane l)
        {
            float2 a0 = as_f2(acc0), a1 = as_f2(acc1), a2 = as_f2(acc2), a3 = as_f2(acc3);
            pool0 += fmaxf(a0.x + a0.y + cb0, 0.f);
            pool1 += fmaxf(a1.x + a1.y + cb1, 0.f);
            pool2 += fmaxf(a2.x + a2.y + cb2, 0.f);
            pool3 += fmaxf(a3.x + a3.y + cb3, 0.f);
        }
    }

    // warp-reduce over the 32 lanes (sum over this half's 256 l positions)
#pragma unroll
    for (int off = 16; off > 0; off >>= 1) {
        pool0 += __shfl_xor_sync(0xffffffffu, pool0, off);
        pool1 += __shfl_xor_sync(0xffffffffu, pool1, off);
        pool2 += __shfl_xor_sync(0xffffffffu, pool2, off);
        pool3 += __shfl_xor_sync(0xffffffffu, pool3, off);
    }
    if (lane == 0) {
        float* dst = g_partial + (b * 2 + h) * 32 + o0;
        dst[0] = pool0;
        dst[1] = pool1;
        dst[2] = pool2;
        dst[3] = pool3;
    }
}

// ============================================================================
// Kernel 2 (fused): delta computation + bilinear gather + patch projection.
// grid (A, B): one block per (b,a) tile. 256 threads, 8 warps.
// Warp 0 computes delta(b,a) = 4*tanh(mean-pooled @ lin_w[a] + lin_b[a])
// while the other warps stage wp_w into smem.
// Warp w owns n in [8w, 8w+8); lane owns d = lane*4 + {0,128}.
// out[((b*64+n)*64 + a)*256 + d] = sum_p samp[n,p]*wp_w[d,p] + wp_b[d]
// ============================================================================
__global__ __launch_bounds__(256) void patch_kernel(const float* __restrict__ x,
                                                    const float* __restrict__ lin_w,
                                                    const float* __restrict__ lin_b,
                                                    const float* __restrict__ wp_w,
                                                    const float* __restrict__ wp_b,
                                                    float* __restrict__ out) {
    __shared__ float s_samp[PPP][NNCH];
    __shared__ float s_wp[PPP][DDD];
    __shared__ float s_delta;

    const int t = threadIdx.x;
    const int a = blockIdx.x, b = blockIdx.y;
    const int w = t >> 5, lane = t & 31;

    // warp 0: compute delta for this (b,a). lanes 0..31 each own channel c.
    if (w == 0) {
        float pooled = (g_partial[(b * 2 + 0) * 32 + lane] +
                        g_partial[(b * 2 + 1) * 32 + lane]) *
                       (1.0f / 512.0f);
        float term = pooled * lin_w[a * 32 + lane];
#pragma unroll
        for (int off = 16; off > 0; off >>= 1)
            term += __shfl_xor_sync(0xffffffffu, term, off);
        if (lane == 0) s_delta = 4.0f * tanhf(term + lin_b[a]);
    }

    // all warps: stage wp_w (D,P) -> s_wp[p][d]; coalesced global read
    for (int u = t; u < DDD * PPP; u += 256) s_wp[u & 15][u >> 4] = wp_w[u];
    __syncthreads();

    // bilinear sampling into s_samp[p][n]
    {
        const float delta = s_delta;
        const int n = t & 63;
        const int pq = t >> 6;  // 0..3
        const float* xb = x + (size_t)b * LL * NNCH;
#pragma unroll
        for (int j = 0; j < 4; j++) {
            int p = pq * 4 + j;
            float xs = (float)(a * 8) + delta + (float)p - 7.5f;
            xs = fminf(fmaxf(xs, 0.f), 511.f);
            float fl = floorf(xs);
            int i0 = (int)fl;
            float f = xs - fl;
            int i1 = min(i0 + 1, LL - 1);
            s_samp[p][n] = xb[i0 * NNCH + n] * (1.0f - f) + xb[i1 * NNCH + n] * f;
        }
    }
    __syncthreads();

    const float4* wb4 = reinterpret_cast<const float4*>(wp_b);
    float4 bias0 = wb4[lane];       // d = lane*4 .. +3
    float4 bias1 = wb4[lane + 32];  // d = 128 + lane*4 .. +3
    ulonglong2 bb0 = as_ull2(bias0), bb1 = as_ull2(bias1);

    unsigned long long acc[8][4];
#pragma unroll
    for (int r = 0; r < 8; r++) {
        acc[r][0] = bb0.x;
        acc[r][1] = bb0.y;
        acc[r][2] = bb1.x;
        acc[r][3] = bb1.y;
    }

#pragma unroll
    for (int p = 0; p < PPP; p++) {
        float4 w0 = *reinterpret_cast<const float4*>(&s_wp[p][lane * 4]);
        float4 w1 = *reinterpret_cast<const float4*>(&s_wp[p][128 + lane * 4]);
        ulonglong2 wA = as_ull2(w0), wB = as_ull2(w1);
#pragma unroll
        for (int r = 0; r < 8; r++) {
            float s = s_samp[p][w * 8 + r];  // broadcast LDS
            unsigned int sb = __float_as_uint(s);
            unsigned long long s2 = ((unsigned long long)sb << 32) | sb;
            fma2(acc[r][0], s2, wA.x);
            fma2(acc[r][1], s2, wA.y);
            fma2(acc[r][2], s2, wB.x);
            fma2(acc[r][3], s2, wB.y);
        }
    }

#pragma unroll
    for (int r = 0; r < 8; r++) {
        const int n = w * 8 + r;
        float* op = out + (((size_t)(b * 64 + n) * 64 + a) * 256);
        float2 l0 = as_f2(acc[r][0]), l1 = as_f2(acc[r][1]);
        float2 h0 = as_f2(acc[r][2]), h1 = as_f2(acc[r][3]);
        float4 v0 = make_float4(l0.x, l0.y, l1.x, l1.y);
        float4 v1 = make_float4(h0.x, h0.y, h1.x, h1.y);
        __stcs(reinterpret_cast<float4*>(op + lane * 4), v0);
        __stcs(reinterpret_cast<float4*>(op + 128 + lane * 4), v1);
    }
}

// ============================================================================
extern "C" void kernel_launch(void* const* d_in, const int* in_sizes, int n_in,
                              void* d_out, int out_size) {
    const float* x = (const float*)d_in[0];
    const float* conv_w = (const float*)d_in[1];
    const float* conv_b = (const float*)d_in[2];
    const float* lin_w = (const float*)d_in[3];
    const float* lin_b = (const float*)d_in[4];
    const float* wp_w = (const float*)d_in[5];
    const float* wp_b = (const float*)d_in[6];

    conv_pool_kernel<<<dim3(2, BB), 256>>>(x, conv_w, conv_b);
    patch_kernel<<<dim3(AAA, BB), 256>>>(x, lin_w, lin_b, wp_w, wp_b, (float*)d_out);
}